// round 6
// baseline (speedup 1.0000x reference)
#include <cuda_runtime.h>
#include <cstdint>
#include <cstddef>

#define FULLMASK 0xffffffffu

// ---------------- problem constants ----------------
constexpr int Bc  = 2;
constexpr int Hc  = 8;
constexpr int Sc  = 2048;
constexpr int Dc  = 128;
constexpr int Mc  = 32768;
constexpr int NQ  = Bc * Sc;       // 4096 queries per head
// ---------------- tiling ----------------
constexpr int TQ  = 128;           // queries per block
constexpr int TK  = 128;           // keys per tile
constexpr int DCH = 32;            // d-chunk staged in shared
constexpr int NTILES = Mc / TK;    // 256
constexpr int NCH = Dc / DCH;      // 4

// smem float offsets
constexpr int OFF_QS = 0;                       // [Dc][TQ]     16384 floats
constexpr int OFF_KS = OFF_QS + Dc * TQ;        // [2][DCH][TK]  8192 floats
constexpr int OFF_LS = OFF_KS + 2 * DCH * TK;   // [TQ][16]      2048 floats
constexpr int OFF_LI = OFF_LS + TQ * 16;        // [TQ][16]      2048 ints
constexpr int SMEM_FLOATS = OFF_LI + TQ * 16;   // 28672 floats = 112 KB

// ---------------- packed fp32x2 helpers (Blackwell full-rate fp32) ----------
static __device__ __forceinline__ void fma2(unsigned long long& acc,
                                            unsigned long long a,
                                            unsigned long long b) {
    asm("fma.rn.f32x2 %0, %1, %2, %0;" : "+l"(acc) : "l"(a), "l"(b));
}
static __device__ __forceinline__ unsigned long long pack2(float a) {
    unsigned long long r;
    asm("mov.b64 %0, {%1, %1};" : "=l"(r) : "f"(a));
    return r;
}
static __device__ __forceinline__ float2 unpack2(unsigned long long v) {
    float2 r;
    asm("mov.b64 {%0, %1}, %2;" : "=f"(r.x), "=f"(r.y) : "l"(v));
    return r;
}

__global__ __launch_bounds__(256, 2)
void praxis_fused_kernel(const float* __restrict__ Q,      // [B,H,S,D]
                         const float* __restrict__ Outp,   // [B,H,S,D]
                         const float* __restrict__ Gate,   // [H]
                         const float* __restrict__ Kmem,   // [H,M,D] (pre-normalized)
                         const float* __restrict__ Vmem,   // [H,M,D]
                         float* __restrict__ Out)          // [B,H,S,D]
{
    extern __shared__ float smem[];
    float* Qs = smem + OFF_QS;
    float* Ks = smem + OFF_KS;
    float* Ls = smem + OFF_LS;
    int*   Li = reinterpret_cast<int*>(smem + OFF_LI);

    const int tid  = threadIdx.x;
    const int tx   = tid & 15;         // key group   (16 x 8 keys)
    const int ty   = tid >> 4;         // query group (16 x 8 queries)
    const int lane = tid & 31;
    const int h    = blockIdx.y;
    const int q0   = blockIdx.x * TQ;

    const float* KH = Kmem + (size_t)h * Mc * Dc;

    // ---------------- init top-k lists ----------------
    #pragma unroll
    for (int i = tid; i < TQ * 16; i += 256) { Ls[i] = -1e30f; Li[i] = 0x7fffffff; }

    // ---- load + l2-normalize Q tile into Qs[d][q] --------------------------
    // Numerically VERBATIM from the R2 kernel (passed at 9.8e-8): 4 lanes per
    // row, identical float4 sum expression, reduced xor1+xor2. qn and all sims
    // are bit-identical to the passing kernel. Do not reassociate.
    #pragma unroll
    for (int half = 0; half < 2; ++half) {
        const int q    = tid >> 2;          // 0..63
        const int part = tid & 3;           // quarter of the 128-dim vector
        const int qrow = half * 64 + q;
        const int qg   = q0 + qrow;
        const int bq   = qg >> 11;          // qg / 2048
        const int sq   = qg & 2047;
        const float* qp = Q + ((((size_t)bq * Hc + h) * Sc + sq) * Dc) + part * 32;
        float4 v[8];
        float ss = 0.f;
        #pragma unroll
        for (int r = 0; r < 8; ++r) {
            v[r] = reinterpret_cast<const float4*>(qp)[r];
            ss += v[r].x * v[r].x + v[r].y * v[r].y + v[r].z * v[r].z + v[r].w * v[r].w;
        }
        ss += __shfl_xor_sync(FULLMASK, ss, 1);
        ss += __shfl_xor_sync(FULLMASK, ss, 2);
        const float inv = 1.0f / fmaxf(sqrtf(ss), 1e-12f);
        #pragma unroll
        for (int r = 0; r < 8; ++r) {
            const int d = part * 32 + r * 4;
            Qs[(d + 0) * TQ + qrow] = v[r].x * inv;
            Qs[(d + 1) * TQ + qrow] = v[r].y * inv;
            Qs[(d + 2) * TQ + qrow] = v[r].z * inv;
            Qs[(d + 3) * TQ + qrow] = v[r].w * inv;
        }
    }

    // copy-lane assignment for K staging (transpose on the fly)
    const int ck = tid & 127;          // key row within tile
    const int cg = tid >> 7;           // 0..1

    // ---------------- prologue: stage (tile 0, chunk 0) ----------------
    {
        const float* src = KH + (size_t)ck * Dc + cg * 4;
        #pragma unroll
        for (int m = 0; m < 4; ++m) {
            const float4 p = *reinterpret_cast<const float4*>(src + 8 * m);
            const int dd = cg * 4 + 8 * m;
            Ks[(dd + 0) * TK + ck] = p.x;
            Ks[(dd + 1) * TK + ck] = p.y;
            Ks[(dd + 2) * TK + ck] = p.z;
            Ks[(dd + 3) * TK + ck] = p.w;
        }
    }
    __syncthreads();

    float thr[8];
    #pragma unroll
    for (int i = 0; i < 8; ++i) thr[i] = -1e30f;
    const unsigned hm = (lane < 16) ? 0x0000FFFFu : 0xFFFF0000u;

    unsigned long long acc[8][4];
    #pragma unroll
    for (int i = 0; i < 8; ++i)
        #pragma unroll
        for (int j = 0; j < 4; ++j) acc[i][j] = 0ULL;

    int buf = 0;

    // ---------------- main loop over key tiles ----------------
    for (int kt = 0; kt < NTILES; ++kt) {
        #pragma unroll 1
        for (int c = 0; c < NCH; ++c) {
            // prefetch next chunk into registers
            const int nc  = (c + 1) & 3;
            const int nkt = kt + ((c + 1) >> 2);
            const bool hn = (nkt < NTILES);
            float4 pf0, pf1, pf2, pf3;
            if (hn) {
                const float* src = KH + ((size_t)(nkt * TK + ck)) * Dc + nc * DCH + cg * 4;
                pf0 = *reinterpret_cast<const float4*>(src + 0);
                pf1 = *reinterpret_cast<const float4*>(src + 8);
                pf2 = *reinterpret_cast<const float4*>(src + 16);
                pf3 = *reinterpret_cast<const float4*>(src + 24);
            }

            // compute this chunk: 8q x 8k per thread, packed f32x2.
            // Each sim is one fma.rn chain over d ascending -- same
            // accumulation order as the passing R2 kernel.
            const float* ksb = Ks + buf * (DCH * TK);
            #pragma unroll
            for (int dd = 0; dd < DCH; ++dd) {
                const int gd = c * DCH + dd;
                const float4 av0 = *reinterpret_cast<const float4*>(Qs + gd * TQ + 8 * ty);
                const float4 av1 = *reinterpret_cast<const float4*>(Qs + gd * TQ + 8 * ty + 4);
                const float* kr = ksb + dd * TK;
                const ulonglong2 b0 = *reinterpret_cast<const ulonglong2*>(kr + 8 * tx);
                const ulonglong2 b1 = *reinterpret_cast<const ulonglong2*>(kr + 8 * tx + 4);
                #define PX_ROW(i, aval)                                         \
                {   unsigned long long aa = pack2(aval);                        \
                    fma2(acc[i][0], aa, b0.x); fma2(acc[i][1], aa, b0.y);       \
                    fma2(acc[i][2], aa, b1.x); fma2(acc[i][3], aa, b1.y); }
                PX_ROW(0, av0.x) PX_ROW(1, av0.y) PX_ROW(2, av0.z) PX_ROW(3, av0.w)
                PX_ROW(4, av1.x) PX_ROW(5, av1.y) PX_ROW(6, av1.z) PX_ROW(7, av1.w)
                #undef PX_ROW
            }

            // drain prefetch into the other buffer (transposed)
            if (hn) {
                float* kd = Ks + (buf ^ 1) * (DCH * TK);
                const int db = cg * 4;
                kd[(db + 0)  * TK + ck] = pf0.x;  kd[(db + 1)  * TK + ck] = pf0.y;
                kd[(db + 2)  * TK + ck] = pf0.z;  kd[(db + 3)  * TK + ck] = pf0.w;
                kd[(db + 8)  * TK + ck] = pf1.x;  kd[(db + 9)  * TK + ck] = pf1.y;
                kd[(db + 10) * TK + ck] = pf1.z;  kd[(db + 11) * TK + ck] = pf1.w;
                kd[(db + 16) * TK + ck] = pf2.x;  kd[(db + 17) * TK + ck] = pf2.y;
                kd[(db + 18) * TK + ck] = pf2.z;  kd[(db + 19) * TK + ck] = pf2.w;
                kd[(db + 24) * TK + ck] = pf3.x;  kd[(db + 25) * TK + ck] = pf3.y;
                kd[(db + 26) * TK + ck] = pf3.z;  kd[(db + 27) * TK + ck] = pf3.w;
            }
            __syncthreads();
            buf ^= 1;
        }

        // ---------------- top-16 update for this tile ----------------
        // Tie rule matches jax.lax.top_k: order by (score desc, index asc).
        // Admission uses >=; min-entry search picks smallest score with
        // LARGEST index among equals; replacement on equal score only if the
        // candidate index is lower. Insertion order is therefore irrelevant.
        const int kbase = kt * TK;
        #pragma unroll
        for (int i = 0; i < 8; ++i) {
            const float2 u0 = unpack2(acc[i][0]);
            const float2 u1 = unpack2(acc[i][1]);
            const float2 u2 = unpack2(acc[i][2]);
            const float2 u3 = unpack2(acc[i][3]);
            float sims[8] = { u0.x, u0.y, u1.x, u1.y, u2.x, u2.y, u3.x, u3.y };

            float mx = sims[0];
            #pragma unroll
            for (int jj = 1; jj < 8; ++jj) mx = fmaxf(mx, sims[jj]);
            const unsigned bal = __ballot_sync(FULLMASK, mx >= thr[i]);
            if (bal) {
                const int row = ty * 8 + i;          // tile-local q row
                #pragma unroll
                for (int jj = 0; jj < 8; ++jj) {
                    const float s = sims[jj];
                    const int kidx = kbase + 8 * tx + jj;
                    bool pending = s >= thr[i];
                    unsigned ball;
                    while ((ball = __ballot_sync(FULLMASK, pending)) != 0) {
                        const unsigned bh = ball & hm;
                        const int src = bh ? (__ffs(bh) - 1) : lane;
                        float newthr = thr[i];
                        if (bh && lane == src) {
                            // leader: find min entry (smallest score; among
                            // equals, largest index), tie-aware replace
                            float* lrow = Ls + row * 16;
                            int*   irow = Li + row * 16;
                            float mn = lrow[0]; int mj = 0; int mi = irow[0];
                            #pragma unroll
                            for (int j = 1; j < 16; ++j) {
                                const float v = lrow[j];
                                const int  vi = irow[j];
                                if (v < mn || (v == mn && vi > mi)) {
                                    mn = v; mj = j; mi = vi;
                                }
                            }
                            if (s > mn || (s == mn && kidx < mi)) {
                                lrow[mj] = s; irow[mj] = kidx;
                            }
                            float t = lrow[0];
                            #pragma unroll
                            for (int j = 1; j < 16; ++j) t = fminf(t, lrow[j]);
                            newthr = t;
                        }
                        __syncwarp(FULLMASK);
                        const float bc = __shfl_sync(FULLMASK, newthr, src);
                        if (bh) {
                            thr[i] = bc;
                            if (lane == src) pending = false;   // leader retired
                            pending = pending && (s >= thr[i]);
                        }
                    }
                }
            }
            acc[i][0] = 0ULL; acc[i][1] = 0ULL; acc[i][2] = 0ULL; acc[i][3] = 0ULL;
        }
    }

    // ---------------- epilogue: gather V, weighted sum, gate blend ----------
    __syncthreads();
    const float gv = Gate[h];
    const float g  = 1.0f / (1.0f + expf(-gv));
    const float og = 1.0f - g;
    const float* VH = Vmem + (size_t)h * Mc * Dc;

    const int r    = tid >> 1;          // row within tile (0..127)
    const int part = tid & 1;           // which 64-dim half

    float4 a[16];
    #pragma unroll
    for (int m = 0; m < 16; ++m) a[m] = make_float4(0.f, 0.f, 0.f, 0.f);

    #pragma unroll 1
    for (int j = 0; j < 16; ++j) {
        const float sj = Ls[r * 16 + j];
        const int   vj = Li[r * 16 + j];
        const float4* vp = reinterpret_cast<const float4*>(VH + (size_t)vj * Dc + part * 64);
        #pragma unroll
        for (int m = 0; m < 16; ++m) {
            const float4 v = vp[m];
            a[m].x += sj * v.x; a[m].y += sj * v.y;
            a[m].z += sj * v.z; a[m].w += sj * v.w;
        }
    }

    {
        const int qg = q0 + r;
        const int bq = qg >> 11;
        const int sq = qg & 2047;
        const size_t off = (((size_t)bq * Hc + h) * Sc + sq) * Dc + part * 64;
        #pragma unroll
        for (int m = 0; m < 16; ++m) {
            const float4 o = *reinterpret_cast<const float4*>(Outp + off + 4 * m);
            float4 rr;
            rr.x = g * a[m].x + og * o.x;
            rr.y = g * a[m].y + og * o.y;
            rr.z = g * a[m].z + og * o.z;
            rr.w = g * a[m].w + og * o.w;
            *reinterpret_cast<float4*>(Out + off + 4 * m) = rr;
        }
    }
}

extern "C" void kernel_launch(void* const* d_in, const int* in_sizes, int n_in,
                              void* d_out, int out_size) {
    // metadata order: inputs(0), query(1), key(2), value(3), outputs(4),
    //                 gate(5), key_memories(6), value_memories(7)
    const float* query   = (const float*)d_in[1];
    const float* outputs = (const float*)d_in[4];
    const float* gate    = (const float*)d_in[5];
    const float* kmem    = (const float*)d_in[6];
    const float* vmem    = (const float*)d_in[7];
    float* out = (float*)d_out;

    const int smem_bytes = SMEM_FLOATS * (int)sizeof(float);   // 112 KB
    cudaFuncSetAttribute(praxis_fused_kernel,
                         cudaFuncAttributeMaxDynamicSharedMemorySize, smem_bytes);

    dim3 grid(NQ / TQ, Hc);   // 32 x 8 = 256 blocks -> single wave at occupancy 2
    praxis_fused_kernel<<<grid, 256, smem_bytes>>>(query, outputs, gate, kmem, vmem, out);
}

// round 7
// speedup vs baseline: 1.2042x; 1.2042x over previous
#include <cuda_runtime.h>
#include <cstdint>
#include <cstddef>

#define FULLMASK 0xffffffffu

// ---------------- problem constants ----------------
constexpr int Bc  = 2;
constexpr int Hc  = 8;
constexpr int Sc  = 2048;
constexpr int Dc  = 128;
constexpr int Mc  = 32768;
constexpr int NQ  = Bc * Sc;        // 4096 queries per head
// ---------------- tiling ----------------
constexpr int TQ  = 128;            // queries per block
constexpr int TK  = 128;            // keys per tile
constexpr int DCH = 16;             // dims staged per pipeline stage
constexpr int KSTRIDE = 20;         // padded floats per key row (80B, 16B aligned)
constexpr int NCHUNK = Dc / DCH;    // 8 stages per key tile
constexpr int NTILES = Mc / TK;     // 256
constexpr int NST = NTILES * NCHUNK;// 2048 pipeline stages
constexpr int KBUF = TK * KSTRIDE;  // 2560 floats per K buffer

// smem float offsets
constexpr int OFF_QS = 0;                       // [Dc][TQ]        16384
constexpr int OFF_KS = OFF_QS + Dc * TQ;        // [3][TK][KSTRIDE] 7680
constexpr int OFF_LS = OFF_KS + 3 * KBUF;       // [TQ][16]         2048
constexpr int OFF_LI = OFF_LS + TQ * 16;        // [TQ][16]         2048
constexpr int OFF_TH = OFF_LI + TQ * 16;        // [TQ]              128
constexpr int SMEM_FLOATS = OFF_TH + TQ;        // 28288 floats = 113152 B

// ---------------- packed fp32x2 helpers (Blackwell full-rate fp32) ----------
static __device__ __forceinline__ void fma2(unsigned long long& acc,
                                            unsigned long long a,
                                            unsigned long long b) {
    asm("fma.rn.f32x2 %0, %1, %2, %0;" : "+l"(acc) : "l"(a), "l"(b));
}
static __device__ __forceinline__ unsigned long long pack2(float a) {
    unsigned long long r;
    asm("mov.b64 %0, {%1, %1};" : "=l"(r) : "f"(a));
    return r;
}
static __device__ __forceinline__ float2 unpack2(unsigned long long v) {
    float2 r;
    asm("mov.b64 {%0, %1}, %2;" : "=f"(r.x), "=f"(r.y) : "l"(v));
    return r;
}
static __device__ __forceinline__ void cpasync16(uint32_t dst, const void* src) {
    asm volatile("cp.async.cg.shared.global [%0], [%1], 16;" :: "r"(dst), "l"(src));
}
static __device__ __forceinline__ void cp_commit() {
    asm volatile("cp.async.commit_group;" ::: "memory");
}
static __device__ __forceinline__ void cp_wait1() {
    asm volatile("cp.async.wait_group 1;" ::: "memory");
}

__global__ __launch_bounds__(256, 2)
void praxis_fused_kernel(const float* __restrict__ Q,      // [B,H,S,D]
                         const float* __restrict__ Outp,   // [B,H,S,D]
                         const float* __restrict__ Gate,   // [H]
                         const float* __restrict__ Kmem,   // [H,M,D] (pre-normalized)
                         const float* __restrict__ Vmem,   // [H,M,D]
                         float* __restrict__ Out)          // [B,H,S,D]
{
    extern __shared__ float smem[];
    float* Qs = smem + OFF_QS;
    float* Ks = smem + OFF_KS;
    float* Ls = smem + OFF_LS;
    int*   Li = reinterpret_cast<int*>(smem + OFF_LI);
    float* Th = smem + OFF_TH;

    const int tid  = threadIdx.x;
    const int tx   = tid & 15;         // key group (16); keys tx + 16j
    const int ty   = tid >> 4;         // query group (16): queries 8ty..8ty+7
    const int lane = tid & 31;
    const int h    = blockIdx.y;
    const int q0   = blockIdx.x * TQ;

    const float* KH = Kmem + (size_t)h * Mc * Dc;

    // ---------------- init top-k lists + thresholds ----------------
    #pragma unroll
    for (int i = tid; i < TQ * 16; i += 256) { Ls[i] = -1e30f; Li[i] = 0x7fffffff; }
    if (tid < TQ) Th[tid] = -1e30f;

    // ---- load + l2-normalize Q tile into Qs[d][q] --------------------------
    // Numerically VERBATIM from the R2/R6 kernels (rel_err ~1e-7): 4 lanes per
    // row, identical float4 sum expression, reduced xor1+xor2. Do not touch.
    #pragma unroll
    for (int half = 0; half < 2; ++half) {
        const int q    = tid >> 2;          // 0..63
        const int part = tid & 3;           // quarter of the 128-dim vector
        const int qrow = half * 64 + q;
        const int qg   = q0 + qrow;
        const int bq   = qg >> 11;
        const int sq   = qg & 2047;
        const float* qp = Q + ((((size_t)bq * Hc + h) * Sc + sq) * Dc) + part * 32;
        float4 v[8];
        float ss = 0.f;
        #pragma unroll
        for (int r = 0; r < 8; ++r) {
            v[r] = reinterpret_cast<const float4*>(qp)[r];
            ss += v[r].x * v[r].x + v[r].y * v[r].y + v[r].z * v[r].z + v[r].w * v[r].w;
        }
        ss += __shfl_xor_sync(FULLMASK, ss, 1);
        ss += __shfl_xor_sync(FULLMASK, ss, 2);
        const float inv = 1.0f / fmaxf(sqrtf(ss), 1e-12f);
        #pragma unroll
        for (int r = 0; r < 8; ++r) {
            const int d = part * 32 + r * 4;
            Qs[(d + 0) * TQ + qrow] = v[r].x * inv;
            Qs[(d + 1) * TQ + qrow] = v[r].y * inv;
            Qs[(d + 2) * TQ + qrow] = v[r].z * inv;
            Qs[(d + 3) * TQ + qrow] = v[r].w * inv;
        }
    }

    // ---------------- cp.async staging setup ----------------
    const uint32_t ks_u32 = (uint32_t)__cvta_generic_to_shared(Ks);
    const int r0  = tid >> 2;           // key row 0..63 (and r0+64)
    const int seg = tid & 3;            // 16B segment of the 64B chunk row

    // stage st covers tile st>>3, dims (st&7)*16 .. +15. Each thread copies
    // 2x16B: rows r0 and r0+64, segment seg.
    #define ISSUE_STAGE(st, buf)                                                 \
    {   const int _tile = (st) >> 3, _c = (st) & 7;                              \
        const float* _s = KH + ((size_t)(_tile * TK + r0)) * Dc + _c * DCH + seg * 4; \
        const uint32_t _d = ks_u32 + (uint32_t)((buf) * KBUF + r0 * KSTRIDE + seg * 4) * 4u; \
        cpasync16(_d, _s);                                                       \
        cpasync16(_d + (uint32_t)(64 * KSTRIDE * 4), _s + (size_t)64 * Dc);      \
        cp_commit();                                                             \
    }

    // prologue: stages 0,1 into buffers 0,1
    ISSUE_STAGE(0, 0)
    ISSUE_STAGE(1, 1)

    unsigned long long acc[4][8];       // [q-pair][key]; lanes = (q even, q odd)
    #pragma unroll
    for (int p = 0; p < 4; ++p)
        #pragma unroll
        for (int j = 0; j < 8; ++j) acc[p][j] = 0ULL;

    const unsigned hm = (lane < 16) ? 0x0000FFFFu : 0xFFFF0000u;
    const float* qbase = Qs + 8 * ty;

    int cbuf = 0, ibuf = 2;

    // ---------------- main pipeline over 2048 stages ----------------
    for (int st = 0; st < NST; ++st) {
        cp_wait1();                 // stage st complete (<=1 group pending)
        __syncthreads();            // cross-thread visibility + buffer reuse

        // -- compute stage st: dims (st&7)*16 .. +15, all 128 keys of tile --
        {
            const float* ksb = Ks + cbuf * KBUF;
            const int c = st & 7;
            #pragma unroll
            for (int g = 0; g < 4; ++g) {
                const int d0 = c * DCH + g * 4;
                ulonglong2 u01[4], u23[4];
                #pragma unroll
                for (int e = 0; e < 4; ++e) {
                    const float* qp = qbase + (d0 + e) * TQ;
                    u01[e] = *reinterpret_cast<const ulonglong2*>(qp);      // pairs q0q1,q2q3
                    u23[e] = *reinterpret_cast<const ulonglong2*>(qp + 4);  // pairs q4q5,q6q7
                }
                #pragma unroll
                for (int jb = 0; jb < 2; ++jb) {
                    float4 kv[4];
                    #pragma unroll
                    for (int j = 0; j < 4; ++j)
                        kv[j] = *reinterpret_cast<const float4*>(
                            ksb + (tx + 16 * (jb * 4 + j)) * KSTRIDE + g * 4);
                    #pragma unroll
                    for (int j = 0; j < 4; ++j) {
                        const int jj = jb * 4 + j;
                        #define STEP(comp, e)                                    \
                        {   unsigned long long aa = pack2(kv[j].comp);           \
                            fma2(acc[0][jj], aa, u01[e].x);                      \
                            fma2(acc[1][jj], aa, u01[e].y);                      \
                            fma2(acc[2][jj], aa, u23[e].x);                      \
                            fma2(acc[3][jj], aa, u23[e].y); }
                        STEP(x, 0) STEP(y, 1) STEP(z, 2) STEP(w, 3)
                        #undef STEP
                    }
                }
            }
        }

        // -- issue stage st+2 into ibuf (buffer freed: computed at st-1) --
        if (st + 2 < NST) { ISSUE_STAGE(st + 2, ibuf) }
        else              { cp_commit(); }   // keep group-count invariant

        cbuf = (cbuf == 2) ? 0 : cbuf + 1;
        ibuf = (ibuf == 2) ? 0 : ibuf + 1;

        // -- end of tile: top-16 update (tie rule = (score desc, index asc)) --
        if ((st & 7) == 7) {
            const int kt = st >> 3;
            const int kbase = kt * TK;
            #pragma unroll
            for (int i = 0; i < 8; ++i) {
                const int p = i >> 1;
                float sims[8];
                #pragma unroll
                for (int j = 0; j < 8; ++j) {
                    const float2 u = unpack2(acc[p][j]);
                    sims[j] = (i & 1) ? u.y : u.x;
                }
                const int row = ty * 8 + i;
                float throw_ = Th[row];          // broadcast LDS per half-warp

                float mx = sims[0];
                #pragma unroll
                for (int jj = 1; jj < 8; ++jj) mx = fmaxf(mx, sims[jj]);
                const unsigned bal = __ballot_sync(FULLMASK, mx >= throw_);
                if (bal) {
                    #pragma unroll
                    for (int jj = 0; jj < 8; ++jj) {
                        const float s = sims[jj];
                        const int kidx = kbase + tx + 16 * jj;
                        bool pending = s >= throw_;
                        unsigned ball;
                        while ((ball = __ballot_sync(FULLMASK, pending)) != 0) {
                            const unsigned bh = ball & hm;
                            const int src = bh ? (__ffs(bh) - 1) : lane;
                            float newthr = throw_;
                            if (bh && lane == src) {
                                float* lrow = Ls + row * 16;
                                int*   irow = Li + row * 16;
                                float mn = lrow[0]; int mj = 0; int mi = irow[0];
                                #pragma unroll
                                for (int j = 1; j < 16; ++j) {
                                    const float v = lrow[j];
                                    const int  vi = irow[j];
                                    if (v < mn || (v == mn && vi > mi)) {
                                        mn = v; mj = j; mi = vi;
                                    }
                                }
                                if (s > mn || (s == mn && kidx < mi)) {
                                    lrow[mj] = s; irow[mj] = kidx;
                                }
                                float t = lrow[0];
                                #pragma unroll
                                for (int j = 1; j < 16; ++j) t = fminf(t, lrow[j]);
                                newthr = t;
                            }
                            __syncwarp(FULLMASK);
                            const float bc = __shfl_sync(FULLMASK, newthr, src);
                            throw_ = bc;                    // own-half value when bh, else unchanged
                            if (bh) {
                                if (lane == src) pending = false;
                                pending = pending && (s >= throw_);
                            }
                        }
                    }
                    if ((lane & 15) == 0) Th[row] = throw_;
                }
            }
            #pragma unroll
            for (int p = 0; p < 4; ++p)
                #pragma unroll
                for (int j = 0; j < 8; ++j) acc[p][j] = 0ULL;
        }
    }
    #undef ISSUE_STAGE

    // ---------------- epilogue: gather V, weighted sum, gate blend ----------
    __syncthreads();
    const float gv = Gate[h];
    const float g  = 1.0f / (1.0f + expf(-gv));
    const float og = 1.0f - g;
    const float* VH = Vmem + (size_t)h * Mc * Dc;

    const int r    = tid >> 1;          // row within tile (0..127)
    const int part = tid & 1;           // which 64-dim half

    float4 a[16];
    #pragma unroll
    for (int m = 0; m < 16; ++m) a[m] = make_float4(0.f, 0.f, 0.f, 0.f);

    #pragma unroll 1
    for (int j = 0; j < 16; ++j) {
        const float sj = Ls[r * 16 + j];
        const int   vj = Li[r * 16 + j];
        const float4* vp = reinterpret_cast<const float4*>(VH + (size_t)vj * Dc + part * 64);
        #pragma unroll
        for (int m = 0; m < 16; ++m) {
            const float4 v = vp[m];
            a[m].x += sj * v.x; a[m].y += sj * v.y;
            a[m].z += sj * v.z; a[m].w += sj * v.w;
        }
    }

    {
        const int qg = q0 + r;
        const int bq = qg >> 11;
        const int sq = qg & 2047;
        const size_t off = (((size_t)bq * Hc + h) * Sc + sq) * Dc + part * 64;
        #pragma unroll
        for (int m = 0; m < 16; ++m) {
            const float4 o = *reinterpret_cast<const float4*>(Outp + off + 4 * m);
            float4 rr;
            rr.x = g * a[m].x + og * o.x;
            rr.y = g * a[m].y + og * o.y;
            rr.z = g * a[m].z + og * o.z;
            rr.w = g * a[m].w + og * o.w;
            *reinterpret_cast<float4*>(Out + off + 4 * m) = rr;
        }
    }
}

extern "C" void kernel_launch(void* const* d_in, const int* in_sizes, int n_in,
                              void* d_out, int out_size) {
    // metadata order: inputs(0), query(1), key(2), value(3), outputs(4),
    //                 gate(5), key_memories(6), value_memories(7)
    const float* query   = (const float*)d_in[1];
    const float* outputs = (const float*)d_in[4];
    const float* gate    = (const float*)d_in[5];
    const float* kmem    = (const float*)d_in[6];
    const float* vmem    = (const float*)d_in[7];
    float* out = (float*)d_out;

    const int smem_bytes = SMEM_FLOATS * (int)sizeof(float);   // 113152 B
    cudaFuncSetAttribute(praxis_fused_kernel,
                         cudaFuncAttributeMaxDynamicSharedMemorySize, smem_bytes);

    dim3 grid(NQ / TQ, Hc);   // 32 x 8 = 256 blocks -> single wave at occupancy 2
    praxis_fused_kernel<<<grid, 256, smem_bytes>>>(query, outputs, gate, kmem, vmem, out);
}